// round 13
// baseline (speedup 1.0000x reference)
#include <cuda_runtime.h>
#include <cuda_fp16.h>
#include <cstdint>
#include <cstddef>

// Problem constants
#define B_ 4
#define S_ 2048
#define D_ 1024
#define H_ 16
#define DH_ 64
#define M_ (B_ * S_)      // 8192
#define N_QKV (3 * D_)    // 3072

// Scratch (device globals — no allocation allowed)
__device__ __half g_qh[(size_t)B_ * H_ * S_ * DH_];   // Q pre-scaled 0.125*log2e
__device__ __half g_kh[(size_t)B_ * H_ * S_ * DH_];
__device__ __half g_vh[(size_t)B_ * H_ * S_ * DH_];
__device__ __half g_ctxh[(size_t)M_ * D_];            // [B,S,D]
__device__ __half g_xh[(size_t)M_ * D_];
__device__ __half g_wqkvh[(size_t)N_QKV * D_];
__device__ __half g_wouth[(size_t)D_ * D_];

// ---------------------------------------------------------------------------
// helpers
// ---------------------------------------------------------------------------
__device__ __forceinline__ void mma_f16(float* c, const uint32_t* a,
                                        const uint32_t* b) {
    asm volatile(
        "mma.sync.aligned.m16n8k16.row.col.f32.f16.f16.f32 "
        "{%0,%1,%2,%3}, {%4,%5,%6,%7}, {%8,%9}, {%0,%1,%2,%3};"
        : "+f"(c[0]), "+f"(c[1]), "+f"(c[2]), "+f"(c[3])
        : "r"(a[0]), "r"(a[1]), "r"(a[2]), "r"(a[3]), "r"(b[0]), "r"(b[1]));
}
__device__ __forceinline__ uint32_t smem_u32(const void* p) {
    uint32_t a;
    asm("{ .reg .u64 t; cvta.to.shared.u64 t, %1; cvt.u32.u64 %0, t; }"
        : "=r"(a) : "l"(p));
    return a;
}
__device__ __forceinline__ void cp16(uint32_t dst, const void* src) {
    asm volatile("cp.async.ca.shared.global [%0], [%1], 16;"
                 :: "r"(dst), "l"(src));
}
#define CP_COMMIT() asm volatile("cp.async.commit_group;" ::: "memory")
#define CP_WAIT(n)  asm volatile("cp.async.wait_group %0;" :: "n"(n) : "memory")

__device__ __forceinline__ uint32_t h2u(float lo, float hi) {
    __half2 h = __floats2half2_rn(lo, hi);
    return *(uint32_t*)&h;
}
__device__ __forceinline__ float ex2f(float x) {
    float y;
    asm("ex2.approx.f32 %0, %1;" : "=f"(y) : "f"(x));
    return y;
}
__device__ __forceinline__ void ldsm_x4(uint32_t& r0, uint32_t& r1,
                                        uint32_t& r2, uint32_t& r3,
                                        uint32_t addr) {
    asm volatile("ldmatrix.sync.aligned.m8n8.x4.shared.b16 {%0,%1,%2,%3}, [%4];"
                 : "=r"(r0), "=r"(r1), "=r"(r2), "=r"(r3) : "r"(addr));
}
__device__ __forceinline__ void ldsm_x4_trans(uint32_t& r0, uint32_t& r1,
                                              uint32_t& r2, uint32_t& r3,
                                              uint32_t addr) {
    asm volatile("ldmatrix.sync.aligned.m8n8.x4.trans.shared.b16 {%0,%1,%2,%3}, [%4];"
                 : "=r"(r0), "=r"(r1), "=r"(r2), "=r"(r3) : "r"(addr));
}

// ---------------------------------------------------------------------------
// fp32 -> fp16 pre-pass
// ---------------------------------------------------------------------------
__global__ void f2h_kernel(const float* __restrict__ src,
                           __half* __restrict__ dst, int n4)
{
    const int i = blockIdx.x * blockDim.x + threadIdx.x;
    if (i < n4) {
        float4 v = ((const float4*)src)[i];
        __half2* d = (__half2*)dst + 2 * i;
        d[0] = __floats2half2_rn(v.x, v.y);
        d[1] = __floats2half2_rn(v.z, v.w);
    }
}

// ---------------------------------------------------------------------------
// fp16 tensor-core GEMM — frozen R9 config (measured optimum: 157 us):
// CTA 128x128, BK=64, 8 warps (2m x 4n), warp tile 64x32, m16n8k16.
// 2-stage cp.async.ca, 1 barrier/chunk, ldmatrix.x4 fragments. 2 CTAs/SM.
// ---------------------------------------------------------------------------
#define RSTR 36           // words per padded row (72 halves = 144 B)
#define STAGE_B 36864u    // bytes per stage (A 18432 + B 18432)
#define GEMM_SMEM (2 * 36864)

template <int EPI>
__global__ __launch_bounds__(256, 2) void mma_gemm_h(
    const __half* __restrict__ A, const __half* __restrict__ W,
    const float* __restrict__ bias, float* __restrict__ C,
    int N, int K)
{
    extern __shared__ uint32_t dsm[];
    const uint32_t smb = smem_u32(dsm);

    const int tid = threadIdx.x;
    const int wid = tid >> 5;
    const int lane = tid & 31;
    const int g = lane >> 2;
    const int t = lane & 3;
    const int m0 = (wid >> 2) * 64;
    const int n0 = (wid & 3) * 32;

    const int bm = blockIdx.y * 128;
    const int bn = blockIdx.x * 128;

    const __half* Ag = A + (size_t)bm * K;
    const __half* Wg = W + (size_t)bn * K;

    const int lr  = tid >> 3;
    const int lc8 = tid & 7;
    uint32_t soff[4];
#pragma unroll
    for (int q = 0; q < 4; q++)
        soff[q] = (uint32_t)(lr + 32 * q) * (RSTR * 4) + lc8 * 16;

    uint32_t aAddr[4];
#pragma unroll
    for (int mt = 0; mt < 4; mt++) {
        const int row = m0 + mt * 16 + (lane & 7) + ((lane >> 3) & 1) * 8;
        aAddr[mt] = smb + (uint32_t)row * (RSTR * 4) + ((lane >> 4) * 16);
    }
    uint32_t bAddr[2];
#pragma unroll
    for (int p = 0; p < 2; p++) {
        const int row = n0 + p * 16 + ((lane >> 4) * 8) + (lane & 7);
        bAddr[p] = smb + 18432u + (uint32_t)row * (RSTR * 4) +
                   (((lane >> 3) & 1) * 16);
    }

    float c[4][4][4];
#pragma unroll
    for (int i = 0; i < 4; i++)
#pragma unroll
        for (int j = 0; j < 4; j++)
#pragma unroll
            for (int q = 0; q < 4; q++) c[i][j][q] = 0.0f;

#pragma unroll
    for (int q = 0; q < 4; q++) {
        const int r = lr + 32 * q;
        cp16(smb + soff[q], Ag + (size_t)r * K + lc8 * 8);
        cp16(smb + 18432u + soff[q], Wg + (size_t)r * K + lc8 * 8);
    }
    CP_COMMIT();

    const int NCH = K >> 6;
    for (int ch = 0; ch < NCH; ch++) {
        CP_WAIT(0);
        __syncthreads();

        if (ch + 1 < NCH) {
            const uint32_t sb = smb + (uint32_t)((ch + 1) & 1) * STAGE_B;
            const int kc = (ch + 1) * 64;
#pragma unroll
            for (int q = 0; q < 4; q++) {
                const int r = lr + 32 * q;
                cp16(sb + soff[q], Ag + (size_t)r * K + kc + lc8 * 8);
                cp16(sb + 18432u + soff[q], Wg + (size_t)r * K + kc + lc8 * 8);
            }
            CP_COMMIT();
        }

        const uint32_t st = (uint32_t)(ch & 1) * STAGE_B;
#pragma unroll
        for (int ks = 0; ks < 4; ks++) {
            const uint32_t ko = st + (uint32_t)ks * 32;
            uint32_t afr[4][4];
#pragma unroll
            for (int mt = 0; mt < 4; mt++)
                ldsm_x4(afr[mt][0], afr[mt][1], afr[mt][2], afr[mt][3],
                        aAddr[mt] + ko);
            uint32_t bq[2][4];
#pragma unroll
            for (int p = 0; p < 2; p++)
                ldsm_x4(bq[p][0], bq[p][1], bq[p][2], bq[p][3], bAddr[p] + ko);
#pragma unroll
            for (int mt = 0; mt < 4; mt++)
#pragma unroll
                for (int nt = 0; nt < 4; nt++) {
                    uint32_t bfr[2] = {bq[nt >> 1][(nt & 1) * 2],
                                       bq[nt >> 1][(nt & 1) * 2 + 1]};
                    mma_f16(c[mt][nt], afr[mt], bfr);
                }
        }
    }

#pragma unroll
    for (int mt = 0; mt < 4; mt++) {
#pragma unroll
        for (int half = 0; half < 2; half++) {
            const int m = bm + m0 + mt * 16 + g + half * 8;
#pragma unroll
            for (int nt = 0; nt < 4; nt++) {
                const int n = bn + n0 + nt * 8 + t * 2;
                const float v0 = c[mt][nt][half * 2 + 0] + bias[n + 0];
                const float v1 = c[mt][nt][half * 2 + 1] + bias[n + 1];
                if (EPI == 0) {
                    *(float2*)(C + (size_t)m * N + n) = make_float2(v0, v1);
                } else {
                    const int bb = m >> 11;
                    const int s  = m & 2047;
                    const int cg = n >> 10;
                    const int h  = (n & 1023) >> 6;
                    const int d  = n & 63;
                    const float sc = (cg == 0) ? 0.18033688f : 1.0f;
                    __half* dst = (cg == 0) ? g_qh : ((cg == 1) ? g_kh : g_vh);
                    __half2 o = __floats2half2_rn(v0 * sc, v1 * sc);
                    *(__half2*)(dst + (((size_t)(bb * H_ + h)) * S_ + s) * DH_ + d) = o;
                }
            }
        }
    }
}

// ---------------------------------------------------------------------------
// fp16 flash attention, 256-row Q tile: 512 threads, 16 warps x 16 rows.
// Halves K/V L2 traffic vs 128-row tiles. 3-stage K/V ring, 1 barrier/chunk.
// Q in registers; K via ldmatrix.x4; V via ldmatrix.x4.trans.
// Stage = K(9216B)+V(9216B); smem 3*18432 = 55296 B. 1 CTA (512 thr)/SM.
// Softmax log2-domain (Q pre-scaled by log2e/8), raw ex2.approx.
// ---------------------------------------------------------------------------
#define ASTAGE_B 18432u
#define ATT_SMEM (3 * 18432)
#define QROWS 256

__global__ __launch_bounds__(512, 1) void attn_mma_h(__half* __restrict__ ctx)
{
    extern __shared__ uint32_t smw[];
    const uint32_t smb = smem_u32(smw);

    const int qb = (int)gridDim.x - 1 - (int)blockIdx.x;  // heavy tiles first
    const int bh = blockIdx.y;
    const int b  = bh >> 4;
    const int h  = bh & 15;
    const size_t base = (size_t)bh * (S_ * DH_);
    const int q0 = qb * QROWS;

    const int tid  = threadIdx.x;
    const int wid  = tid >> 5;      // 0..15
    const int lane = tid & 31;
    const int g = lane >> 2;
    const int t = lane & 3;
    const int aw = 16 * wid + g;    // 0..255
    const int row0 = q0 + aw;

    // loaders: K/V tile = 64 rows x 8 groups = 512 cp16 each; 1 per thread
    const int lr  = tid >> 3;       // 0..63
    const int lc8 = tid & 7;
    const uint32_t soff = (uint32_t)lr * (RSTR * 4) + lc8 * 16;

    // ---- preload K/V chunks 0,1 into stages 0,1 (nch = 4(qb+1) >= 4) ----
#pragma unroll
    for (int pc = 0; pc < 2; pc++) {
        const uint32_t sb = smb + (uint32_t)pc * ASTAGE_B;
        const size_t kbase = base + (size_t)pc * 64 * DH_;
        cp16(sb + soff, g_kh + kbase + (size_t)lr * DH_ + lc8 * 8);
        cp16(sb + 9216u + soff, g_vh + kbase + (size_t)lr * DH_ + lc8 * 8);
        CP_COMMIT();
    }

    // ---- Q fragments in registers ----
    uint32_t qa[4][4];
    {
        const __half* qp = g_qh + base + (size_t)row0 * DH_ + 2 * t;
        const __half* qp8 = qp + 8 * DH_;
#pragma unroll
        for (int ks = 0; ks < 4; ks++) {
            qa[ks][0] = *(const uint32_t*)(qp + ks * 16);
            qa[ks][1] = *(const uint32_t*)(qp8 + ks * 16);
            qa[ks][2] = *(const uint32_t*)(qp + ks * 16 + 8);
            qa[ks][3] = *(const uint32_t*)(qp8 + ks * 16 + 8);
        }
    }

    // K ldmatrix per-lane offsets (relative to stage base)
    uint32_t kAddr[4];
#pragma unroll
    for (int p = 0; p < 4; p++) {
        const int row = p * 16 + ((lane >> 4) * 8) + (lane & 7);
        kAddr[p] = (uint32_t)row * (RSTR * 4) + (((lane >> 3) & 1) * 16);
    }
    // V x4.trans per-lane offsets
    uint32_t vAddr[4];
    {
        const uint32_t kr = (uint32_t)((lane & 7) + ((lane >> 3) & 1) * 8);
        const uint32_t col = (uint32_t)((lane >> 4) * 16);
#pragma unroll
        for (int p = 0; p < 4; p++)
            vAddr[p] = 9216u + kr * (RSTR * 4) + col + (uint32_t)p * 32;
    }

    float o[8][4];
#pragma unroll
    for (int nt = 0; nt < 8; nt++)
#pragma unroll
        for (int j = 0; j < 4; j++) o[nt][j] = 0.0f;
    float m0r = -1e30f, m1r = -1e30f, l0r = 0.0f, l1r = 0.0f;

    const int nch = (QROWS / 64) * (qb + 1);   // 4(qb+1)
    int st_r = 0, st_w = 2;
    for (int c = 0; c < nch; c++) {
        if (c + 1 < nch) { CP_WAIT(1); } else { CP_WAIT(0); }
        __syncthreads();

        if (c + 2 < nch) {
            const uint32_t sb = smb + (uint32_t)st_w * ASTAGE_B;
            const size_t kbase = base + (size_t)(c + 2) * 64 * DH_;
            cp16(sb + soff, g_kh + kbase + (size_t)lr * DH_ + lc8 * 8);
            cp16(sb + 9216u + soff, g_vh + kbase + (size_t)lr * DH_ + lc8 * 8);
            CP_COMMIT();
        }
        st_w = (st_w == 2) ? 0 : st_w + 1;

        const uint32_t stb = smb + (uint32_t)st_r * ASTAGE_B;
        st_r = (st_r == 2) ? 0 : st_r + 1;

        // ---- S = Q K^T (log2-domain scores) ----
        float s[8][4];
#pragma unroll
        for (int nt = 0; nt < 8; nt++)
#pragma unroll
            for (int j = 0; j < 4; j++) s[nt][j] = 0.0f;

#pragma unroll
        for (int ks = 0; ks < 4; ks++) {
            const uint32_t ko = stb + (uint32_t)ks * 32;
#pragma unroll
            for (int p = 0; p < 4; p++) {
                uint32_t kq[4];
                ldsm_x4(kq[0], kq[1], kq[2], kq[3], kAddr[p] + ko);
                {
                    uint32_t bfr[2] = {kq[0], kq[1]};
                    mma_f16(s[2 * p], qa[ks], bfr);
                }
                {
                    uint32_t bfr[2] = {kq[2], kq[3]};
                    mma_f16(s[2 * p + 1], qa[ks], bfr);
                }
            }
        }

        // ---- causal mask (only where chunk crosses this warp's rows) ----
        if (c * 64 + 63 > row0) {
            const int r1 = row0 + 8;
            const int colb = c * 64 + 2 * t;
#pragma unroll
            for (int nt = 0; nt < 8; nt++) {
                const int col = colb + 8 * nt;
                if (col > row0)     s[nt][0] = -1e30f;
                if (col + 1 > row0) s[nt][1] = -1e30f;
                if (col > r1)       s[nt][2] = -1e30f;
                if (col + 1 > r1)   s[nt][3] = -1e30f;
            }
        }

        // ---- online softmax (base-2) ----
        float mn0 = -1e30f, mn1 = -1e30f;
#pragma unroll
        for (int nt = 0; nt < 8; nt++) {
            mn0 = fmaxf(mn0, fmaxf(s[nt][0], s[nt][1]));
            mn1 = fmaxf(mn1, fmaxf(s[nt][2], s[nt][3]));
        }
        mn0 = fmaxf(mn0, __shfl_xor_sync(0xffffffffu, mn0, 1));
        mn0 = fmaxf(mn0, __shfl_xor_sync(0xffffffffu, mn0, 2));
        mn1 = fmaxf(mn1, __shfl_xor_sync(0xffffffffu, mn1, 1));
        mn1 = fmaxf(mn1, __shfl_xor_sync(0xffffffffu, mn1, 2));
        const float mN0 = fmaxf(m0r, mn0);
        const float mN1 = fmaxf(m1r, mn1);
        const float sc0 = ex2f(m0r - mN0);
        const float sc1 = ex2f(m1r - mN1);
        m0r = mN0; m1r = mN1;

        float rs0 = 0.0f, rs1 = 0.0f;
#pragma unroll
        for (int nt = 0; nt < 8; nt++) {
            s[nt][0] = ex2f(s[nt][0] - mN0); rs0 += s[nt][0];
            s[nt][1] = ex2f(s[nt][1] - mN0); rs0 += s[nt][1];
            s[nt][2] = ex2f(s[nt][2] - mN1); rs1 += s[nt][2];
            s[nt][3] = ex2f(s[nt][3] - mN1); rs1 += s[nt][3];
        }
        rs0 += __shfl_xor_sync(0xffffffffu, rs0, 1);
        rs0 += __shfl_xor_sync(0xffffffffu, rs0, 2);
        rs1 += __shfl_xor_sync(0xffffffffu, rs1, 1);
        rs1 += __shfl_xor_sync(0xffffffffu, rs1, 2);
        l0r = l0r * sc0 + rs0;
        l1r = l1r * sc1 + rs1;
#pragma unroll
        for (int nt = 0; nt < 8; nt++) {
            o[nt][0] *= sc0; o[nt][1] *= sc0;
            o[nt][2] *= sc1; o[nt][3] *= sc1;
        }

        // ---- O += P V ----
#pragma unroll
        for (int ks = 0; ks < 4; ks++) {
            uint32_t a[4];
            a[0] = h2u(s[2 * ks][0],     s[2 * ks][1]);
            a[1] = h2u(s[2 * ks][2],     s[2 * ks][3]);
            a[2] = h2u(s[2 * ks + 1][0], s[2 * ks + 1][1]);
            a[3] = h2u(s[2 * ks + 1][2], s[2 * ks + 1][3]);
            const uint32_t vk = stb + (uint32_t)(ks * 16) * (RSTR * 4);
#pragma unroll
            for (int p = 0; p < 4; p++) {
                uint32_t b0, b1, b2, b3;
                ldsm_x4_trans(b0, b1, b2, b3, vk + vAddr[p]);
                {
                    uint32_t bfr[2] = {b0, b1};
                    mma_f16(o[2 * p], a, bfr);
                }
                {
                    uint32_t bfr[2] = {b2, b3};
                    mma_f16(o[2 * p + 1], a, bfr);
                }
            }
        }
    }

    // ---- epilogue: ctx halves ----
    const float inv0 = 1.0f / l0r;
    const float inv1 = 1.0f / l1r;
    __half* dst0 = ctx + ((size_t)(b * S_) + row0) * D_ + h * DH_ + 2 * t;
    __half* dst1 = dst0 + 8 * D_;
#pragma unroll
    for (int nt = 0; nt < 8; nt++) {
        *(__half2*)(dst0 + 8 * nt) = __floats2half2_rn(o[nt][0] * inv0, o[nt][1] * inv0);
        *(__half2*)(dst1 + 8 * nt) = __floats2half2_rn(o[nt][2] * inv1, o[nt][3] * inv1);
    }
}

// ---------------------------------------------------------------------------
extern "C" void kernel_launch(void* const* d_in, const int* in_sizes, int n_in,
                              void* d_out, int out_size)
{
    const float* x     = (const float*)d_in[0];
    // d_in[1] = mask (causal, implied) — unused
    const float* w_qkv = (const float*)d_in[2];
    const float* b_qkv = (const float*)d_in[3];
    const float* w_out = (const float*)d_in[4];
    const float* b_out = (const float*)d_in[5];
    float* out = (float*)d_out;

    __half *ctx_ptr, *x_ptr, *wqkv_ptr, *wout_ptr;
    cudaGetSymbolAddress((void**)&ctx_ptr, g_ctxh);
    cudaGetSymbolAddress((void**)&x_ptr, g_xh);
    cudaGetSymbolAddress((void**)&wqkv_ptr, g_wqkvh);
    cudaGetSymbolAddress((void**)&wout_ptr, g_wouth);

    // 0) fp16 conversion pre-pass
    {
        const int n4x = M_ * D_ / 4;
        f2h_kernel<<<(n4x + 255) / 256, 256>>>(x, x_ptr, n4x);
        const int n4w = N_QKV * D_ / 4;
        f2h_kernel<<<(n4w + 255) / 256, 256>>>(w_qkv, wqkv_ptr, n4w);
        const int n4o = D_ * D_ / 4;
        f2h_kernel<<<(n4o + 255) / 256, 256>>>(w_out, wout_ptr, n4o);
    }

    // 1) QKV projection with scatter epilogue (frozen R9 config)
    {
        cudaFuncSetAttribute(mma_gemm_h<1>,
                             cudaFuncAttributeMaxDynamicSharedMemorySize, GEMM_SMEM);
        dim3 grid(N_QKV / 128, M_ / 128);
        mma_gemm_h<1><<<grid, 256, GEMM_SMEM>>>(x_ptr, wqkv_ptr, b_qkv, nullptr,
                                                N_QKV, D_);
    }

    // 2) Causal flash attention (256-row Q tiles, 512 threads)
    {
        cudaFuncSetAttribute(attn_mma_h,
                             cudaFuncAttributeMaxDynamicSharedMemorySize, ATT_SMEM);
        dim3 grid(S_ / QROWS, B_ * H_);
        attn_mma_h<<<grid, 512, ATT_SMEM>>>(ctx_ptr);
    }

    // 3) Output projection (frozen R9 config)
    {
        cudaFuncSetAttribute(mma_gemm_h<0>,
                             cudaFuncAttributeMaxDynamicSharedMemorySize, GEMM_SMEM);
        dim3 grid(D_ / 128, M_ / 128);
        mma_gemm_h<0><<<grid, 256, GEMM_SMEM>>>(ctx_ptr, wout_ptr, b_out, out,
                                                D_, D_);
    }
}

// round 14
// speedup vs baseline: 1.0930x; 1.0930x over previous
#include <cuda_runtime.h>
#include <cuda_fp16.h>
#include <cstdint>
#include <cstddef>

// Problem constants
#define B_ 4
#define S_ 2048
#define D_ 1024
#define H_ 16
#define DH_ 64
#define M_ (B_ * S_)      // 8192
#define N_QKV (3 * D_)    // 3072

// Scratch (device globals — no allocation allowed)
__device__ __half g_qh[(size_t)B_ * H_ * S_ * DH_];   // Q pre-scaled 0.125*log2e
__device__ __half g_kh[(size_t)B_ * H_ * S_ * DH_];
__device__ __half g_vh[(size_t)B_ * H_ * S_ * DH_];
__device__ __half g_ctxh[(size_t)M_ * D_];            // [B,S,D]
__device__ __half g_xh[(size_t)M_ * D_];
__device__ __half g_wqkvh[(size_t)N_QKV * D_];
__device__ __half g_wouth[(size_t)D_ * D_];

// ---------------------------------------------------------------------------
// helpers
// ---------------------------------------------------------------------------
__device__ __forceinline__ void mma_f16(float* c, const uint32_t* a,
                                        const uint32_t* b) {
    asm volatile(
        "mma.sync.aligned.m16n8k16.row.col.f32.f16.f16.f32 "
        "{%0,%1,%2,%3}, {%4,%5,%6,%7}, {%8,%9}, {%0,%1,%2,%3};"
        : "+f"(c[0]), "+f"(c[1]), "+f"(c[2]), "+f"(c[3])
        : "r"(a[0]), "r"(a[1]), "r"(a[2]), "r"(a[3]), "r"(b[0]), "r"(b[1]));
}
__device__ __forceinline__ uint32_t smem_u32(const void* p) {
    uint32_t a;
    asm("{ .reg .u64 t; cvta.to.shared.u64 t, %1; cvt.u32.u64 %0, t; }"
        : "=r"(a) : "l"(p));
    return a;
}
__device__ __forceinline__ void cp16(uint32_t dst, const void* src) {
    asm volatile("cp.async.ca.shared.global [%0], [%1], 16;"
                 :: "r"(dst), "l"(src));
}
#define CP_COMMIT() asm volatile("cp.async.commit_group;" ::: "memory")
#define CP_WAIT(n)  asm volatile("cp.async.wait_group %0;" :: "n"(n) : "memory")

__device__ __forceinline__ float ex2f(float x) {
    float y;
    asm("ex2.approx.f32 %0, %1;" : "=f"(y) : "f"(x));
    return y;
}
// pack two floats (lo, hi) to f16x2 and exp2 both in one MUFU op
__device__ __forceinline__ uint32_t ex2_h2(float lo, float hi) {
    uint32_t h, r;
    asm("cvt.rn.f16x2.f32 %0, %1, %2;" : "=r"(h) : "f"(hi), "f"(lo));
    asm("ex2.approx.f16x2 %0, %1;" : "=r"(r) : "r"(h));
    return r;
}
__device__ __forceinline__ void ldsm_x4(uint32_t& r0, uint32_t& r1,
                                        uint32_t& r2, uint32_t& r3,
                                        uint32_t addr) {
    asm volatile("ldmatrix.sync.aligned.m8n8.x4.shared.b16 {%0,%1,%2,%3}, [%4];"
                 : "=r"(r0), "=r"(r1), "=r"(r2), "=r"(r3) : "r"(addr));
}
__device__ __forceinline__ void ldsm_x4_trans(uint32_t& r0, uint32_t& r1,
                                              uint32_t& r2, uint32_t& r3,
                                              uint32_t addr) {
    asm volatile("ldmatrix.sync.aligned.m8n8.x4.trans.shared.b16 {%0,%1,%2,%3}, [%4];"
                 : "=r"(r0), "=r"(r1), "=r"(r2), "=r"(r3) : "r"(addr));
}

// ---------------------------------------------------------------------------
// fp32 -> fp16 pre-pass: single launch for x, w_qkv, w_out
// ---------------------------------------------------------------------------
#define N4X (M_ * D_ / 4)
#define N4W (N_QKV * D_ / 4)
#define N4O (D_ * D_ / 4)

__global__ void f2h_all(const float* __restrict__ x, __half* __restrict__ xh,
                        const float* __restrict__ wq, __half* __restrict__ wqh,
                        const float* __restrict__ wo, __half* __restrict__ woh)
{
    const int i = blockIdx.x * blockDim.x + threadIdx.x;
    const float* src;
    __half* dst;
    int off;
    if (i < N4X)            { src = x;  dst = xh;  off = i; }
    else if (i < N4X + N4W) { src = wq; dst = wqh; off = i - N4X; }
    else                    { src = wo; dst = woh; off = i - N4X - N4W; }
    float4 v = ((const float4*)src)[off];
    __half2* d = (__half2*)dst + 2 * off;
    d[0] = __floats2half2_rn(v.x, v.y);
    d[1] = __floats2half2_rn(v.z, v.w);
}

// ---------------------------------------------------------------------------
// fp16 tensor-core GEMM — frozen R9 config (measured optimum: 157 us):
// CTA 128x128, BK=64, 8 warps (2m x 4n), warp tile 64x32, m16n8k16.
// 2-stage cp.async.ca, 1 barrier/chunk, ldmatrix.x4 fragments. 2 CTAs/SM.
// ---------------------------------------------------------------------------
#define RSTR 36           // words per padded row (72 halves = 144 B)
#define STAGE_B 36864u    // bytes per stage (A 18432 + B 18432)
#define GEMM_SMEM (2 * 36864)

template <int EPI>
__global__ __launch_bounds__(256, 2) void mma_gemm_h(
    const __half* __restrict__ A, const __half* __restrict__ W,
    const float* __restrict__ bias, float* __restrict__ C,
    int N, int K)
{
    extern __shared__ uint32_t dsm[];
    const uint32_t smb = smem_u32(dsm);

    const int tid = threadIdx.x;
    const int wid = tid >> 5;
    const int lane = tid & 31;
    const int g = lane >> 2;
    const int t = lane & 3;
    const int m0 = (wid >> 2) * 64;
    const int n0 = (wid & 3) * 32;

    const int bm = blockIdx.y * 128;
    const int bn = blockIdx.x * 128;

    const __half* Ag = A + (size_t)bm * K;
    const __half* Wg = W + (size_t)bn * K;

    const int lr  = tid >> 3;
    const int lc8 = tid & 7;
    uint32_t soff[4];
#pragma unroll
    for (int q = 0; q < 4; q++)
        soff[q] = (uint32_t)(lr + 32 * q) * (RSTR * 4) + lc8 * 16;

    uint32_t aAddr[4];
#pragma unroll
    for (int mt = 0; mt < 4; mt++) {
        const int row = m0 + mt * 16 + (lane & 7) + ((lane >> 3) & 1) * 8;
        aAddr[mt] = smb + (uint32_t)row * (RSTR * 4) + ((lane >> 4) * 16);
    }
    uint32_t bAddr[2];
#pragma unroll
    for (int p = 0; p < 2; p++) {
        const int row = n0 + p * 16 + ((lane >> 4) * 8) + (lane & 7);
        bAddr[p] = smb + 18432u + (uint32_t)row * (RSTR * 4) +
                   (((lane >> 3) & 1) * 16);
    }

    float c[4][4][4];
#pragma unroll
    for (int i = 0; i < 4; i++)
#pragma unroll
        for (int j = 0; j < 4; j++)
#pragma unroll
            for (int q = 0; q < 4; q++) c[i][j][q] = 0.0f;

#pragma unroll
    for (int q = 0; q < 4; q++) {
        const int r = lr + 32 * q;
        cp16(smb + soff[q], Ag + (size_t)r * K + lc8 * 8);
        cp16(smb + 18432u + soff[q], Wg + (size_t)r * K + lc8 * 8);
    }
    CP_COMMIT();

    const int NCH = K >> 6;
    for (int ch = 0; ch < NCH; ch++) {
        CP_WAIT(0);
        __syncthreads();

        if (ch + 1 < NCH) {
            const uint32_t sb = smb + (uint32_t)((ch + 1) & 1) * STAGE_B;
            const int kc = (ch + 1) * 64;
#pragma unroll
            for (int q = 0; q < 4; q++) {
                const int r = lr + 32 * q;
                cp16(sb + soff[q], Ag + (size_t)r * K + kc + lc8 * 8);
                cp16(sb + 18432u + soff[q], Wg + (size_t)r * K + kc + lc8 * 8);
            }
            CP_COMMIT();
        }

        const uint32_t st = (uint32_t)(ch & 1) * STAGE_B;
#pragma unroll
        for (int ks = 0; ks < 4; ks++) {
            const uint32_t ko = st + (uint32_t)ks * 32;
            uint32_t afr[4][4];
#pragma unroll
            for (int mt = 0; mt < 4; mt++)
                ldsm_x4(afr[mt][0], afr[mt][1], afr[mt][2], afr[mt][3],
                        aAddr[mt] + ko);
            uint32_t bq[2][4];
#pragma unroll
            for (int p = 0; p < 2; p++)
                ldsm_x4(bq[p][0], bq[p][1], bq[p][2], bq[p][3], bAddr[p] + ko);
#pragma unroll
            for (int mt = 0; mt < 4; mt++)
#pragma unroll
                for (int nt = 0; nt < 4; nt++) {
                    uint32_t bfr[2] = {bq[nt >> 1][(nt & 1) * 2],
                                       bq[nt >> 1][(nt & 1) * 2 + 1]};
                    mma_f16(c[mt][nt], afr[mt], bfr);
                }
        }
    }

#pragma unroll
    for (int mt = 0; mt < 4; mt++) {
#pragma unroll
        for (int half = 0; half < 2; half++) {
            const int m = bm + m0 + mt * 16 + g + half * 8;
#pragma unroll
            for (int nt = 0; nt < 4; nt++) {
                const int n = bn + n0 + nt * 8 + t * 2;
                const float v0 = c[mt][nt][half * 2 + 0] + bias[n + 0];
                const float v1 = c[mt][nt][half * 2 + 1] + bias[n + 1];
                if (EPI == 0) {
                    *(float2*)(C + (size_t)m * N + n) = make_float2(v0, v1);
                } else {
                    const int bb = m >> 11;
                    const int s  = m & 2047;
                    const int cg = n >> 10;
                    const int h  = (n & 1023) >> 6;
                    const int d  = n & 63;
                    const float sc = (cg == 0) ? 0.18033688f : 1.0f;
                    __half* dst = (cg == 0) ? g_qh : ((cg == 1) ? g_kh : g_vh);
                    __half2 o = __floats2half2_rn(v0 * sc, v1 * sc);
                    *(__half2*)(dst + (((size_t)(bb * H_ + h)) * S_ + s) * DH_ + d) = o;
                }
            }
        }
    }
}

// ---------------------------------------------------------------------------
// fp16 flash attention (R12 structure): 128-row Q tiles, 8 warps x 16 rows,
// 64-key chunks, 3-stage K/V ring, 1 barrier/chunk, 2 CTAs/SM.
// NEW: softmax uses ex2.approx.f16x2 (half the MUFU ops; results ARE the PV
// A-fragments) and the row-sum comes from an extra ones-column MMA
// (no scalar adds, no shuffles).
// ---------------------------------------------------------------------------
#define ASTAGE_B 18432u
#define ATT_SMEM (3 * 18432)

__global__ __launch_bounds__(256, 2) void attn_mma_h(__half* __restrict__ ctx)
{
    extern __shared__ uint32_t smw[];
    const uint32_t smb = smem_u32(smw);

    const int qb = (int)gridDim.x - 1 - (int)blockIdx.x;  // heavy tiles first
    const int bh = blockIdx.y;
    const int b  = bh >> 4;
    const int h  = bh & 15;
    const size_t base = (size_t)bh * (S_ * DH_);
    const int q0 = qb * 128;

    const int tid  = threadIdx.x;
    const int wid  = tid >> 5;
    const int lane = tid & 31;
    const int g = lane >> 2;
    const int t = lane & 3;
    const int aw = 16 * wid + g;
    const int row0 = q0 + aw;

    const int lr  = tid >> 3;
    const int lc8 = tid & 7;
    uint32_t soff[2];
#pragma unroll
    for (int q = 0; q < 2; q++)
        soff[q] = (uint32_t)(lr + 32 * q) * (RSTR * 4) + lc8 * 16;

    // ---- preload K/V chunks 0,1 into stages 0,1 ----
#pragma unroll
    for (int pc = 0; pc < 2; pc++) {
        const uint32_t sb = smb + (uint32_t)pc * ASTAGE_B;
        const size_t kbase = base + (size_t)pc * 64 * DH_;
#pragma unroll
        for (int q = 0; q < 2; q++) {
            const int r = lr + 32 * q;
            cp16(sb + soff[q], g_kh + kbase + (size_t)r * DH_ + lc8 * 8);
            cp16(sb + 9216u + soff[q], g_vh + kbase + (size_t)r * DH_ + lc8 * 8);
        }
        CP_COMMIT();
    }

    // ---- Q fragments in registers ----
    uint32_t qa[4][4];
    {
        const __half* qp = g_qh + base + (size_t)row0 * DH_ + 2 * t;
        const __half* qp8 = qp + 8 * DH_;
#pragma unroll
        for (int ks = 0; ks < 4; ks++) {
            qa[ks][0] = *(const uint32_t*)(qp + ks * 16);
            qa[ks][1] = *(const uint32_t*)(qp8 + ks * 16);
            qa[ks][2] = *(const uint32_t*)(qp + ks * 16 + 8);
            qa[ks][3] = *(const uint32_t*)(qp8 + ks * 16 + 8);
        }
    }

    // K ldmatrix per-lane offsets (relative to stage base)
    uint32_t kAddr[4];
#pragma unroll
    for (int p = 0; p < 4; p++) {
        const int row = p * 16 + ((lane >> 4) * 8) + (lane & 7);
        kAddr[p] = (uint32_t)row * (RSTR * 4) + (((lane >> 3) & 1) * 16);
    }
    // V x4.trans per-lane offsets
    uint32_t vAddr[4];
    {
        const uint32_t kr = (uint32_t)((lane & 7) + ((lane >> 3) & 1) * 8);
        const uint32_t col = (uint32_t)((lane >> 4) * 16);
#pragma unroll
        for (int p = 0; p < 4; p++)
            vAddr[p] = 9216u + kr * (RSTR * 4) + col + (uint32_t)p * 32;
    }

    float o[8][4];
#pragma unroll
    for (int nt = 0; nt < 8; nt++)
#pragma unroll
        for (int j = 0; j < 4; j++) o[nt][j] = 0.0f;
    float m0r = -1e30f, m1r = -1e30f, l0r = 0.0f, l1r = 0.0f;

    const uint32_t ones2 = 0x3C003C00u;   // half2(1,1)
    const uint32_t onesb[2] = {ones2, ones2};

    const int nch = 2 * (qb + 1);
    int st_r = 0, st_w = 2;
    for (int c = 0; c < nch; c++) {
        if (c + 1 < nch) { CP_WAIT(1); } else { CP_WAIT(0); }
        __syncthreads();

        if (c + 2 < nch) {
            const uint32_t sb = smb + (uint32_t)st_w * ASTAGE_B;
            const size_t kbase = base + (size_t)(c + 2) * 64 * DH_;
#pragma unroll
            for (int q = 0; q < 2; q++) {
                const int r = lr + 32 * q;
                cp16(sb + soff[q], g_kh + kbase + (size_t)r * DH_ + lc8 * 8);
                cp16(sb + 9216u + soff[q], g_vh + kbase + (size_t)r * DH_ + lc8 * 8);
            }
            CP_COMMIT();
        }
        st_w = (st_w == 2) ? 0 : st_w + 1;

        const uint32_t stb = smb + (uint32_t)st_r * ASTAGE_B;
        st_r = (st_r == 2) ? 0 : st_r + 1;

        // ---- S = Q K^T (log2-domain scores) ----
        float s[8][4];
#pragma unroll
        for (int nt = 0; nt < 8; nt++)
#pragma unroll
            for (int j = 0; j < 4; j++) s[nt][j] = 0.0f;

#pragma unroll
        for (int ks = 0; ks < 4; ks++) {
            const uint32_t ko = stb + (uint32_t)ks * 32;
#pragma unroll
            for (int p = 0; p < 4; p++) {
                uint32_t kq[4];
                ldsm_x4(kq[0], kq[1], kq[2], kq[3], kAddr[p] + ko);
                {
                    uint32_t bfr[2] = {kq[0], kq[1]};
                    mma_f16(s[2 * p], qa[ks], bfr);
                }
                {
                    uint32_t bfr[2] = {kq[2], kq[3]};
                    mma_f16(s[2 * p + 1], qa[ks], bfr);
                }
            }
        }

        // ---- causal mask (diagonal chunks only) ----
        if (c * 64 + 63 > q0) {
            const int r1 = row0 + 8;
            const int colb = c * 64 + 2 * t;
#pragma unroll
            for (int nt = 0; nt < 8; nt++) {
                const int col = colb + 8 * nt;
                if (col > row0)     s[nt][0] = -1e30f;
                if (col + 1 > row0) s[nt][1] = -1e30f;
                if (col > r1)       s[nt][2] = -1e30f;
                if (col + 1 > r1)   s[nt][3] = -1e30f;
            }
        }

        // ---- online softmax (base-2): max in fp32 ----
        float mn0 = -1e30f, mn1 = -1e30f;
#pragma unroll
        for (int nt = 0; nt < 8; nt++) {
            mn0 = fmaxf(mn0, fmaxf(s[nt][0], s[nt][1]));
            mn1 = fmaxf(mn1, fmaxf(s[nt][2], s[nt][3]));
        }
        mn0 = fmaxf(mn0, __shfl_xor_sync(0xffffffffu, mn0, 1));
        mn0 = fmaxf(mn0, __shfl_xor_sync(0xffffffffu, mn0, 2));
        mn1 = fmaxf(mn1, __shfl_xor_sync(0xffffffffu, mn1, 1));
        mn1 = fmaxf(mn1, __shfl_xor_sync(0xffffffffu, mn1, 2));
        const float mN0 = fmaxf(m0r, mn0);
        const float mN1 = fmaxf(m1r, mn1);
        const float sc0 = ex2f(m0r - mN0);
        const float sc1 = ex2f(m1r - mN1);
        m0r = mN0; m1r = mN1;

        // ---- P = exp2(s - mN) directly in f16x2 (PV A-fragments) ----
        uint32_t pfr[8][2];
#pragma unroll
        for (int nt = 0; nt < 8; nt++) {
            pfr[nt][0] = ex2_h2(s[nt][0] - mN0, s[nt][1] - mN0);
            pfr[nt][1] = ex2_h2(s[nt][2] - mN1, s[nt][3] - mN1);
        }

        // ---- rescale O ----
#pragma unroll
        for (int nt = 0; nt < 8; nt++) {
            o[nt][0] *= sc0; o[nt][1] *= sc0;
            o[nt][2] *= sc1; o[nt][3] *= sc1;
        }

        // ---- O += P V ; row-sums via ones-MMA ----
        float rsum[4] = {0.0f, 0.0f, 0.0f, 0.0f};
#pragma unroll
        for (int ks = 0; ks < 4; ks++) {
            uint32_t a[4] = {pfr[2 * ks][0], pfr[2 * ks][1],
                             pfr[2 * ks + 1][0], pfr[2 * ks + 1][1]};
            mma_f16(rsum, a, onesb);   // P @ ones -> row sums (all cols equal)
            const uint32_t vk = stb + (uint32_t)(ks * 16) * (RSTR * 4);
#pragma unroll
            for (int p = 0; p < 4; p++) {
                uint32_t b0, b1, b2, b3;
                ldsm_x4_trans(b0, b1, b2, b3, vk + vAddr[p]);
                {
                    uint32_t bfr[2] = {b0, b1};
                    mma_f16(o[2 * p], a, bfr);
                }
                {
                    uint32_t bfr[2] = {b2, b3};
                    mma_f16(o[2 * p + 1], a, bfr);
                }
            }
        }
        l0r = l0r * sc0 + rsum[0];
        l1r = l1r * sc1 + rsum[2];
    }

    // ---- epilogue: ctx halves ----
    const float inv0 = 1.0f / l0r;
    const float inv1 = 1.0f / l1r;
    __half* dst0 = ctx + ((size_t)(b * S_) + row0) * D_ + h * DH_ + 2 * t;
    __half* dst1 = dst0 + 8 * D_;
#pragma unroll
    for (int nt = 0; nt < 8; nt++) {
        *(__half2*)(dst0 + 8 * nt) = __floats2half2_rn(o[nt][0] * inv0, o[nt][1] * inv0);
        *(__half2*)(dst1 + 8 * nt) = __floats2half2_rn(o[nt][2] * inv1, o[nt][3] * inv1);
    }
}

// ---------------------------------------------------------------------------
extern "C" void kernel_launch(void* const* d_in, const int* in_sizes, int n_in,
                              void* d_out, int out_size)
{
    const float* x     = (const float*)d_in[0];
    // d_in[1] = mask (causal, implied) — unused
    const float* w_qkv = (const float*)d_in[2];
    const float* b_qkv = (const float*)d_in[3];
    const float* w_out = (const float*)d_in[4];
    const float* b_out = (const float*)d_in[5];
    float* out = (float*)d_out;

    __half *ctx_ptr, *x_ptr, *wqkv_ptr, *wout_ptr;
    cudaGetSymbolAddress((void**)&ctx_ptr, g_ctxh);
    cudaGetSymbolAddress((void**)&x_ptr, g_xh);
    cudaGetSymbolAddress((void**)&wqkv_ptr, g_wqkvh);
    cudaGetSymbolAddress((void**)&wout_ptr, g_wouth);

    // 0) fp16 conversion pre-pass (single launch)
    {
        const int total = N4X + N4W + N4O;
        f2h_all<<<(total + 255) / 256, 256>>>(x, x_ptr, w_qkv, wqkv_ptr,
                                              w_out, wout_ptr);
    }

    // 1) QKV projection with scatter epilogue (frozen R9 config)
    {
        cudaFuncSetAttribute(mma_gemm_h<1>,
                             cudaFuncAttributeMaxDynamicSharedMemorySize, GEMM_SMEM);
        dim3 grid(N_QKV / 128, M_ / 128);
        mma_gemm_h<1><<<grid, 256, GEMM_SMEM>>>(x_ptr, wqkv_ptr, b_qkv, nullptr,
                                                N_QKV, D_);
    }

    // 2) Causal flash attention (R12 config + f16x2 softmax + ones-MMA rowsum)
    {
        cudaFuncSetAttribute(attn_mma_h,
                             cudaFuncAttributeMaxDynamicSharedMemorySize, ATT_SMEM);
        dim3 grid(S_ / 128, B_ * H_);
        attn_mma_h<<<grid, 256, ATT_SMEM>>>(ctx_ptr);
    }

    // 3) Output projection (frozen R9 config)
    {
        cudaFuncSetAttribute(mma_gemm_h<0>,
                             cudaFuncAttributeMaxDynamicSharedMemorySize, GEMM_SMEM);
        dim3 grid(D_ / 128, M_ / 128);
        mma_gemm_h<0><<<grid, 256, GEMM_SMEM>>>(ctx_ptr, wout_ptr, b_out, out,
                                                D_, D_);
    }
}